// round 2
// baseline (speedup 1.0000x reference)
#include <cuda_runtime.h>
#include <math.h>

#define N_ROWS   131072
#define IN_D     12
#define HID      256
#define NL       10
#define OUT_D    3
#define TM       64            // rows per CTA
#define KC       32            // k-chunk of W staged in smem
#define NCHUNK   (HID / KC)    // 8
#define NTHREADS 256

// act: 0=sin 1=cos 2=gauss 3=tanh
__device__ __forceinline__ float actf(float v, int mode) {
    switch (mode) {
        case 0:  return sinf(v);
        case 1:  return cosf(v);
        case 2:  return expf(-v * v);
        default: return tanhf(v);
    }
}

__global__ void __launch_bounds__(NTHREADS, 1)
cppn_kernel(const float* __restrict__ x,
            const float* __restrict__ W0,
            const float* __restrict__ b0,
            const float* __restrict__ Ws,
            const float* __restrict__ bs,
            const float* __restrict__ Wout,
            const float* __restrict__ bout,
            float* __restrict__ out)
{
    extern __shared__ float sm[];
    float* hbuf0 = sm;                      // [HID][TM] activations (transposed: [k][m])
    float* hbuf1 = sm + HID * TM;           // [HID][TM]
    float* wbA   = sm + 2 * HID * TM;       // [KC][HID] weight stage buffer A
    float* wbB   = wbA + KC * HID;          // [KC][HID] weight stage buffer B

    const int tid  = threadIdx.x;
    const int row0 = blockIdx.x * TM;
    const int m0   = (tid & 7) * 8;         // 8 m-rows per thread
    const int n0   = (tid >> 3) * 8;        // 8 n-cols per thread

    float acc[8][8];

    // ======================= layer 0: x(12) -> 256, sin =======================
    {
        // stage W0 (12x256 = 768 float4) into wbA; x tile transposed into wbB as xs[k][m]
        const float4* W0v = (const float4*)W0;
        float4* wa = (float4*)wbA;
        #pragma unroll
        for (int idx = tid; idx < IN_D * HID / 4; idx += NTHREADS) wa[idx] = W0v[idx];
        for (int idx = tid; idx < TM * IN_D; idx += NTHREADS) {
            int m = idx / IN_D, k = idx % IN_D;
            wbB[k * TM + m] = x[(size_t)(row0 + m) * IN_D + k];
        }
        __syncthreads();

        #pragma unroll
        for (int i = 0; i < 8; i++)
            #pragma unroll
            for (int j = 0; j < 8; j++) acc[i][j] = 0.0f;

        #pragma unroll
        for (int k = 0; k < IN_D; k++) {
            const float* hp = wbB + k * TM;
            const float* wp = wbA + k * HID;
            float4 a0 = *(const float4*)(hp + m0);
            float4 a1 = *(const float4*)(hp + m0 + 4);
            float4 w0 = *(const float4*)(wp + n0);
            float4 w1 = *(const float4*)(wp + n0 + 4);
            float a[8] = {a0.x,a0.y,a0.z,a0.w,a1.x,a1.y,a1.z,a1.w};
            float w[8] = {w0.x,w0.y,w0.z,w0.w,w1.x,w1.y,w1.z,w1.w};
            #pragma unroll
            for (int i = 0; i < 8; i++)
                #pragma unroll
                for (int j = 0; j < 8; j++)
                    acc[i][j] = fmaf(a[i], w[j], acc[i][j]);
        }

        // bias + sin -> hbuf0 (transposed store h[n][m])
        float4 bv0 = *(const float4*)(b0 + n0);
        float4 bv1 = *(const float4*)(b0 + n0 + 4);
        float bb[8] = {bv0.x,bv0.y,bv0.z,bv0.w,bv1.x,bv1.y,bv1.z,bv1.w};
        #pragma unroll
        for (int j = 0; j < 8; j++)
            #pragma unroll
            for (int i = 0; i < 8; i++)
                hbuf0[(n0 + j) * TM + m0 + i] = actf(acc[i][j] + bb[j], 0);
    }

    // ======================= hidden layers 1..9: 256 -> 256 ===================
    float* hc = hbuf0;
    float* hn = hbuf1;

    for (int layer = 1; layer < NL; layer++) {
        const float*  W    = Ws + (size_t)(layer - 1) * HID * HID;
        const float*  bias = bs + (layer - 1) * HID;
        const float4* Wv   = (const float4*)W;
        const int mode = layer & 3;

        __syncthreads();   // prior layer fully done before overwriting weight buffers

        #pragma unroll
        for (int i = 0; i < 8; i++)
            #pragma unroll
            for (int j = 0; j < 8; j++) acc[i][j] = 0.0f;

        // preload chunk 0 -> wbA, start chunk 1 -> regs
        float4 pf[8];
        {
            #pragma unroll
            for (int r = 0; r < 8; r++) pf[r] = Wv[r * 256 + tid];
            float4* wd = (float4*)wbA;
            #pragma unroll
            for (int r = 0; r < 8; r++) wd[r * 256 + tid] = pf[r];
            #pragma unroll
            for (int r = 0; r < 8; r++) pf[r] = Wv[2048 + r * 256 + tid];
        }
        __syncthreads();

        #pragma unroll 1
        for (int c = 0; c < NCHUNK; c++) {
            const float* Wbuf = (c & 1) ? wbB : wbA;
            const float* hrow = hc + c * KC * TM;

            #pragma unroll 4
            for (int kk = 0; kk < KC; kk++) {
                const float* hp = hrow + kk * TM;
                const float* wp = Wbuf + kk * HID;
                float4 a0 = *(const float4*)(hp + m0);
                float4 a1 = *(const float4*)(hp + m0 + 4);
                float4 w0 = *(const float4*)(wp + n0);
                float4 w1 = *(const float4*)(wp + n0 + 4);
                float a[8] = {a0.x,a0.y,a0.z,a0.w,a1.x,a1.y,a1.z,a1.w};
                float w[8] = {w0.x,w0.y,w0.z,w0.w,w1.x,w1.y,w1.z,w1.w};
                #pragma unroll
                for (int i = 0; i < 8; i++)
                    #pragma unroll
                    for (int j = 0; j < 8; j++)
                        acc[i][j] = fmaf(a[i], w[j], acc[i][j]);
            }

            if (c + 1 < NCHUNK) {
                __syncthreads();   // everyone done reading the buffer we overwrite
                float4* wd = (float4*)((c & 1) ? wbA : wbB);
                #pragma unroll
                for (int r = 0; r < 8; r++) wd[r * 256 + tid] = pf[r];
                if (c + 2 < NCHUNK) {
                    #pragma unroll
                    for (int r = 0; r < 8; r++)
                        pf[r] = Wv[(c + 2) * 2048 + r * 256 + tid];
                }
                __syncthreads();   // staged chunk visible
            }
        }

        // bias + act -> hn (transposed store)
        float4 bv0 = *(const float4*)(bias + n0);
        float4 bv1 = *(const float4*)(bias + n0 + 4);
        float bb[8] = {bv0.x,bv0.y,bv0.z,bv0.w,bv1.x,bv1.y,bv1.z,bv1.w};
        #pragma unroll
        for (int j = 0; j < 8; j++)
            #pragma unroll
            for (int i = 0; i < 8; i++)
                hn[(n0 + j) * TM + m0 + i] = actf(acc[i][j] + bb[j], mode);

        float* t = hc; hc = hn; hn = t;
    }

    // ======================= output layer: 256 -> 3, sigmoid ==================
    __syncthreads();
    if (tid < TM * OUT_D) {                 // 192 threads: one (row, col) each
        const int m = tid / OUT_D;
        const int j = tid % OUT_D;
        float s = bout[j];
        #pragma unroll 8
        for (int k = 0; k < HID; k++)
            s = fmaf(hc[k * TM + m], Wout[k * OUT_D + j], s);
        out[(size_t)(row0 + m) * OUT_D + j] = 1.0f / (1.0f + expf(-s));
    }
}

extern "C" void kernel_launch(void* const* d_in, const int* in_sizes, int n_in,
                              void* d_out, int out_size)
{
    const float* x    = (const float*)d_in[0];
    const float* W0   = (const float*)d_in[1];
    const float* b0   = (const float*)d_in[2];
    const float* Ws   = (const float*)d_in[3];
    const float* bs   = (const float*)d_in[4];
    const float* Wout = (const float*)d_in[5];
    const float* bout = (const float*)d_in[6];
    float* out = (float*)d_out;

    const int smem_bytes = (2 * HID * TM + 2 * KC * HID) * (int)sizeof(float); // 192 KB
    cudaFuncSetAttribute(cppn_kernel, cudaFuncAttributeMaxDynamicSharedMemorySize, smem_bytes);

    dim3 grid(N_ROWS / TM);   // 2048 CTAs
    dim3 block(NTHREADS);
    cppn_kernel<<<grid, block, smem_bytes>>>(x, W0, b0, Ws, bs, Wout, bout, out);
}

// round 3
// speedup vs baseline: 1.2970x; 1.2970x over previous
#include <cuda_runtime.h>
#include <math.h>

#define N_ROWS   131072
#define IN_D     12
#define HID      256
#define NL       10
#define OUT_D    3
#define TM       64                 // rows per CTA
#define KC       16                 // k-chunk staged per cp.async group
#define NCHUNK   (HID / KC)         // 16 chunks per layer
#define NTHREADS 256
#define TOTAL_CHUNKS ((NL - 1) * NCHUNK)   // 144 flat chunks over hidden layers

// act: 0=sin 1=cos 2=gauss 3=tanh
__device__ __forceinline__ float actf(float v, int mode) {
    switch (mode) {
        case 0:  return sinf(v);
        case 1:  return cosf(v);
        case 2:  return expf(-v * v);
        default: return tanhf(v);
    }
}

// Stage flat chunk tc (16x256 floats) of Ws into wbuf via cp.async (one group).
__device__ __forceinline__ void cp_chunk(const float4* __restrict__ Wv,
                                         int tc, float* wbuf, int tid) {
    const float4* src = Wv + (size_t)tc * (KC * HID / 4) + tid;
    unsigned dst = (unsigned)__cvta_generic_to_shared(wbuf) + tid * 16u;
    #pragma unroll
    for (int r = 0; r < 4; r++) {
        asm volatile("cp.async.cg.shared.global [%0], [%1], 16;\n"
                     :: "r"(dst + r * (NTHREADS * 16u)), "l"(src + r * NTHREADS));
    }
    asm volatile("cp.async.commit_group;\n" ::: "memory");
}

__global__ void __launch_bounds__(NTHREADS, 2)
cppn_kernel(const float* __restrict__ x,
            const float* __restrict__ W0,
            const float* __restrict__ b0,
            const float* __restrict__ Ws,
            const float* __restrict__ bs,
            const float* __restrict__ Wout,
            const float* __restrict__ bout,
            float* __restrict__ out)
{
    extern __shared__ float sm[];
    float* hc  = sm;                    // [HID][TM] activations (transposed [k][m]) 64 KB
    float* wb0 = sm + HID * TM;         // [KC][HID] weight stage buffer 0 (16 KB)
    float* wb1 = wb0 + KC * HID;        // [KC][HID] weight stage buffer 1 (16 KB)

    const int tid  = threadIdx.x;
    const int row0 = blockIdx.x * TM;
    const int m0   = (tid & 7) * 8;     // 8 m-rows per thread
    const int n0   = (tid >> 3) * 8;    // 8 n-cols per thread
    const float4* Wv = (const float4*)Ws;

    float acc[8][8];

    // ---- prologue: start staging hidden chunk 0 into wb0 while layer 0 runs ----
    cp_chunk(Wv, 0, wb0, tid);

    // ======================= layer 0: x(12) -> 256, sin =======================
    {
        // W0 (12x256 floats) + x-transpose (12x64) staged synchronously into wb1 region
        float* w0s = wb1;                       // 12 KB
        float* xs  = wb1 + IN_D * HID;          // 3 KB
        const float4* W0v = (const float4*)W0;
        float4* wa = (float4*)w0s;
        #pragma unroll
        for (int idx = tid; idx < IN_D * HID / 4; idx += NTHREADS) wa[idx] = W0v[idx];
        for (int idx = tid; idx < TM * IN_D; idx += NTHREADS) {
            int m = idx / IN_D, k = idx % IN_D;
            xs[k * TM + m] = x[(size_t)(row0 + m) * IN_D + k];
        }
        __syncthreads();

        #pragma unroll
        for (int i = 0; i < 8; i++)
            #pragma unroll
            for (int j = 0; j < 8; j++) acc[i][j] = 0.0f;

        #pragma unroll
        for (int k = 0; k < IN_D; k++) {
            const float* hp = xs + k * TM;
            const float* wp = w0s + k * HID;
            float4 a0 = *(const float4*)(hp + m0);
            float4 a1 = *(const float4*)(hp + m0 + 4);
            float4 w0v_ = *(const float4*)(wp + n0);
            float4 w1v_ = *(const float4*)(wp + n0 + 4);
            float a[8] = {a0.x,a0.y,a0.z,a0.w,a1.x,a1.y,a1.z,a1.w};
            float w[8] = {w0v_.x,w0v_.y,w0v_.z,w0v_.w,w1v_.x,w1v_.y,w1v_.z,w1v_.w};
            #pragma unroll
            for (int i = 0; i < 8; i++)
                #pragma unroll
                for (int j = 0; j < 8; j++)
                    acc[i][j] = fmaf(a[i], w[j], acc[i][j]);
        }

        // bias + sin -> hc (each thread writes only its own cells; published by
        // the barrier at the top of the first hidden chunk)
        float4 bv0 = *(const float4*)(b0 + n0);
        float4 bv1 = *(const float4*)(b0 + n0 + 4);
        float bb[8] = {bv0.x,bv0.y,bv0.z,bv0.w,bv1.x,bv1.y,bv1.z,bv1.w};
        #pragma unroll
        for (int j = 0; j < 8; j++) {
            float4 v;
            v.x = actf(acc[0][j] + bb[j], 0);
            v.y = actf(acc[1][j] + bb[j], 0);
            v.z = actf(acc[2][j] + bb[j], 0);
            v.w = actf(acc[3][j] + bb[j], 0);
            *(float4*)(hc + (n0 + j) * TM + m0) = v;
            float4 u;
            u.x = actf(acc[4][j] + bb[j], 0);
            u.y = actf(acc[5][j] + bb[j], 0);
            u.z = actf(acc[6][j] + bb[j], 0);
            u.w = actf(acc[7][j] + bb[j], 0);
            *(float4*)(hc + (n0 + j) * TM + m0 + 4) = u;
        }
    }

    // ======================= hidden layers 1..9: 256 -> 256 ===================
    int t = 0;   // flat chunk counter
    for (int layer = 1; layer < NL; layer++) {
        const int mode = layer & 3;

        #pragma unroll
        for (int i = 0; i < 8; i++)
            #pragma unroll
            for (int j = 0; j < 8; j++) acc[i][j] = 0.0f;

        #pragma unroll 1
        for (int c = 0; c < NCHUNK; c++, t++) {
            // chunk t is in flight into wb[t&1]; make it resident + visible
            asm volatile("cp.async.wait_group 0;\n" ::: "memory");
            __syncthreads();
            // start staging chunk t+1 into the other buffer (safe: everyone has
            // passed the barrier, so no one still reads wb[(t+1)&1])
            if (t + 1 < TOTAL_CHUNKS)
                cp_chunk(Wv, t + 1, (t & 1) ? wb0 : wb1, tid);

            const float* Wbuf = (t & 1) ? wb1 : wb0;
            const float* hrow = hc + c * KC * TM;

            #pragma unroll 4
            for (int kk = 0; kk < KC; kk++) {
                const float* hp = hrow + kk * TM;
                const float* wp = Wbuf + kk * HID;
                float4 a0 = *(const float4*)(hp + m0);
                float4 a1 = *(const float4*)(hp + m0 + 4);
                float4 w0v_ = *(const float4*)(wp + n0);
                float4 w1v_ = *(const float4*)(wp + n0 + 4);
                float a[8] = {a0.x,a0.y,a0.z,a0.w,a1.x,a1.y,a1.z,a1.w};
                float w[8] = {w0v_.x,w0v_.y,w0v_.z,w0v_.w,w1v_.x,w1v_.y,w1v_.z,w1v_.w};
                #pragma unroll
                for (int i = 0; i < 8; i++)
                    #pragma unroll
                    for (int j = 0; j < 8; j++)
                        acc[i][j] = fmaf(a[i], w[j], acc[i][j]);
            }
        }

        // epilogue: all reads of hc for this layer done -> overwrite in place
        __syncthreads();
        const float* bias = bs + (layer - 1) * HID;
        float4 bv0 = *(const float4*)(bias + n0);
        float4 bv1 = *(const float4*)(bias + n0 + 4);
        float bb[8] = {bv0.x,bv0.y,bv0.z,bv0.w,bv1.x,bv1.y,bv1.z,bv1.w};
        #pragma unroll
        for (int j = 0; j < 8; j++) {
            float4 v;
            v.x = actf(acc[0][j] + bb[j], mode);
            v.y = actf(acc[1][j] + bb[j], mode);
            v.z = actf(acc[2][j] + bb[j], mode);
            v.w = actf(acc[3][j] + bb[j], mode);
            *(float4*)(hc + (n0 + j) * TM + m0) = v;
            float4 u;
            u.x = actf(acc[4][j] + bb[j], mode);
            u.y = actf(acc[5][j] + bb[j], mode);
            u.z = actf(acc[6][j] + bb[j], mode);
            u.w = actf(acc[7][j] + bb[j], mode);
            *(float4*)(hc + (n0 + j) * TM + m0 + 4) = u;
        }
        // writes are published by the barrier at the top of the next layer's
        // first chunk (or the one below for the output layer)
    }

    // ======================= output layer: 256 -> 3, sigmoid ==================
    __syncthreads();
    if (tid < TM * OUT_D) {                 // 192 threads: one (row, col) each
        const int m = tid / OUT_D;
        const int j = tid % OUT_D;
        float s = bout[j];
        #pragma unroll 8
        for (int k = 0; k < HID; k++)
            s = fmaf(hc[k * TM + m], Wout[k * OUT_D + j], s);
        out[(size_t)(row0 + m) * OUT_D + j] = 1.0f / (1.0f + expf(-s));
    }
}

extern "C" void kernel_launch(void* const* d_in, const int* in_sizes, int n_in,
                              void* d_out, int out_size)
{
    const float* x    = (const float*)d_in[0];
    const float* W0   = (const float*)d_in[1];
    const float* b0   = (const float*)d_in[2];
    const float* Ws   = (const float*)d_in[3];
    const float* bs   = (const float*)d_in[4];
    const float* Wout = (const float*)d_in[5];
    const float* bout = (const float*)d_in[6];
    float* out = (float*)d_out;

    const int smem_bytes = (HID * TM + 2 * KC * HID) * (int)sizeof(float); // 96 KB
    cudaFuncSetAttribute(cppn_kernel, cudaFuncAttributeMaxDynamicSharedMemorySize, smem_bytes);

    dim3 grid(N_ROWS / TM);   // 2048 CTAs, 2 resident per SM
    dim3 block(NTHREADS);
    cppn_kernel<<<grid, block, smem_bytes>>>(x, W0, b0, Ws, bs, Wout, bout, out);
}